// round 1
// baseline (speedup 1.0000x reference)
#include <cuda_runtime.h>
#include <cuda_bf16.h>
#include <math.h>

#define D_MODEL 2048
#define D_STATE 32
#define HEADDIM 128
#define NHEADS 16
#define D_CONVK 4
#define M_PREFIX 8
#define MAX_LOOPS 6
#define BRIDGE_RANK 64
#define VOCAB 50432
#define LORA_RANK 4
#define BSZ 2
#define TLEN 512
#define TE (M_PREFIX + TLEN)     /* 520 */
#define ROWS (BSZ * TE)          /* 1040 */
#define DIN (2*D_MODEL + 2*D_STATE + NHEADS)  /* 4176 */
#define CONV_CH (D_MODEL + 2*D_STATE)         /* 2112 */
#define OUTROWS (BSZ * TLEN)     /* 1024 */

// ---------------- scratch (static device globals; no allocs) ----------------
__device__ float g_Win[DIN * D_MODEL];
__device__ float g_Wout[D_MODEL * D_MODEL];
__device__ float g_xe[ROWS * D_MODEL];
__device__ float g_xp[OUTROWS * D_MODEL];
__device__ float g_zx[ROWS * DIN];
__device__ float g_xbc[ROWS * CONV_CH];
__device__ float g_dt[ROWS * NHEADS];
__device__ float g_dA[ROWS * NHEADS];
__device__ float g_y[ROWS * D_MODEL];
__device__ float g_nrm[ROWS * D_MODEL];
__device__ float g_mo[ROWS * D_MODEL];
__device__ float g_t1[ROWS * BRIDGE_RANK];
__device__ float g_fin[OUTROWS * D_MODEL];

__device__ __forceinline__ float siluf(float x) { return x / (1.0f + expf(-x)); }

// ---------------- LoRA weight fold: W = base + 2 * (B @ A) ----------------
__global__ void k_lora(const float* __restrict__ base, const float* __restrict__ Amat,
                       const float* __restrict__ Bmat, float* __restrict__ W, int rows) {
    int i = blockIdx.x * 256 + threadIdx.x;
    if (i >= rows * D_MODEL) return;
    int r = i / D_MODEL, c = i % D_MODEL;
    float s = 0.f;
#pragma unroll
    for (int q = 0; q < LORA_RANK; q++) s += Bmat[r*LORA_RANK + q] * Amat[q*D_MODEL + c];
    W[i] = base[i] + 2.0f * s;
}

// ---------------- embedding gather + latent prefix ----------------
__global__ void k_embed(const int* __restrict__ ids, const float* __restrict__ emb,
                        const float* __restrict__ latent) {
    int i = blockIdx.x * 256 + threadIdx.x;
    if (i >= ROWS * D_MODEL) return;
    int row = i / D_MODEL, c = i % D_MODEL;
    int b = row / TE, t = row % TE;
    float v;
    if (t < M_PREFIX) {
        v = latent[t * D_MODEL + c];
    } else {
        int tok = ids[b * TLEN + (t - M_PREFIX)];
        v = emb[(long)tok * D_MODEL + c];
        g_xp[(b * TLEN + (t - M_PREFIX)) * D_MODEL + c] = v;
    }
    g_xe[i] = v;
}

// ---------------- lifeline add (t>=M) + interleaved RoPE, in place ----------------
__global__ void k_prerope(const float* __restrict__ gate, float loop_i) {
    int row = blockIdx.x;
    int j = threadIdx.x;              // pair index 0..1023
    int b = row / TE, t = row % TE;
    float v0 = g_xe[row * D_MODEL + 2*j];
    float v1 = g_xe[row * D_MODEL + 2*j + 1];
    if (t >= M_PREFIX) {
        int pr = (b * TLEN + t - M_PREFIX) * D_MODEL;
        v0 += gate[2*j]     * g_xp[pr + 2*j];
        v1 += gate[2*j + 1] * g_xp[pr + 2*j + 1];
    }
    float freq = loop_i * powf(10000.0f, -(float)(2*j) / (float)D_MODEL);
    float s, c;
    sincosf(freq, &s, &c);
    g_xe[row * D_MODEL + 2*j]     = v0 * c - v1 * s;
    g_xe[row * D_MODEL + 2*j + 1] = v1 * c + v0 * s;
}

// ---------------- classic 128x128x16 register-tiled SGEMM, C = A @ B^T ----------------
// A: MxK row-major, B: NxK row-major, C: MxN row-major. K % 16 == 0 assumed.
#define BM 128
#define BN 128
#define BKK 16
#define SSTR 132
__global__ void __launch_bounds__(256) sgemm_nt(const float* __restrict__ A,
                                                const float* __restrict__ B,
                                                float* __restrict__ C,
                                                int M, int N, int K) {
    __shared__ float As[BKK * SSTR];
    __shared__ float Bs[BKK * SSTR];
    int tid = threadIdx.x;
    int tx = tid & 15, ty = tid >> 4;
    int m0 = blockIdx.y * BM, n0 = blockIdx.x * BN;
    float acc[8][8] = {};
    int lr = tid >> 2;          // 0..63
    int lc = (tid & 3) * 4;     // 0,4,8,12

    for (int k0 = 0; k0 < K; k0 += BKK) {
#pragma unroll
        for (int half = 0; half < 2; half++) {
            int row = lr + half * 64;
            int gm = m0 + row;
            float4 va = (gm < M) ? *(const float4*)&A[(long)gm * K + k0 + lc]
                                 : make_float4(0.f, 0.f, 0.f, 0.f);
            As[(lc+0)*SSTR + row] = va.x; As[(lc+1)*SSTR + row] = va.y;
            As[(lc+2)*SSTR + row] = va.z; As[(lc+3)*SSTR + row] = va.w;
            int gn = n0 + row;
            float4 vb = (gn < N) ? *(const float4*)&B[(long)gn * K + k0 + lc]
                                 : make_float4(0.f, 0.f, 0.f, 0.f);
            Bs[(lc+0)*SSTR + row] = vb.x; Bs[(lc+1)*SSTR + row] = vb.y;
            Bs[(lc+2)*SSTR + row] = vb.z; Bs[(lc+3)*SSTR + row] = vb.w;
        }
        __syncthreads();
#pragma unroll
        for (int kk = 0; kk < BKK; kk++) {
            float a[8], b[8];
            *(float4*)&a[0] = *(const float4*)&As[kk*SSTR + ty*8];
            *(float4*)&a[4] = *(const float4*)&As[kk*SSTR + ty*8 + 4];
            *(float4*)&b[0] = *(const float4*)&Bs[kk*SSTR + tx*8];
            *(float4*)&b[4] = *(const float4*)&Bs[kk*SSTR + tx*8 + 4];
#pragma unroll
            for (int i = 0; i < 8; i++)
#pragma unroll
                for (int j = 0; j < 8; j++)
                    acc[i][j] += a[i] * b[j];
        }
        __syncthreads();
    }
#pragma unroll
    for (int i = 0; i < 8; i++) {
        int gm = m0 + ty*8 + i;
        if (gm >= M) continue;
#pragma unroll
        for (int j = 0; j < 8; j++) {
            int gn = n0 + tx*8 + j;
            if (gn < N) C[(long)gm * N + gn] = acc[i][j];
        }
    }
}

// ---------------- dt = softplus(raw + bias), dA = exp(-exp(A_log)*dt) ----------------
__global__ void k_dt(const float* __restrict__ dt_bias, const float* __restrict__ A_log) {
    int i = blockIdx.x * 256 + threadIdx.x;
    if (i >= ROWS * NHEADS) return;
    int row = i / NHEADS, h = i % NHEADS;
    float x = g_zx[(long)row * DIN + (2*D_MODEL + 2*D_STATE) + h] + dt_bias[h];
    float sp = (x > 20.f) ? x : log1pf(expf(x));
    g_dt[i] = sp;
    g_dA[i] = expf(-expf(A_log[h]) * sp);
}

// ---------------- depthwise causal conv (K=4) + bias + silu ----------------
__global__ void k_conv(const float* __restrict__ cw, const float* __restrict__ cb) {
    int i = blockIdx.x * 256 + threadIdx.x;
    if (i >= ROWS * CONV_CH) return;
    int row = i / CONV_CH, c = i % CONV_CH;
    int b = row / TE, t = row % TE;
    float acc = cb[c];
#pragma unroll
    for (int k = 0; k < D_CONVK; k++) {
        int tt = t - (D_CONVK - 1) + k;
        if (tt >= 0) acc += g_zx[((long)(b*TE + tt)) * DIN + D_MODEL + c] * cw[c*D_CONVK + k];
    }
    g_xbc[i] = siluf(acc);
}

// ---------------- sequential SSM scan: 1 CTA per (b,h), 128 p-lanes, N=32 state in regs ----------------
__global__ void k_scan(const float* __restrict__ D_skip) {
    int b = blockIdx.x >> 4;
    int h = blockIdx.x & 15;
    int p = threadIdx.x;
    float hs[D_STATE];
#pragma unroll
    for (int n = 0; n < D_STATE; n++) hs[n] = 0.f;
    __shared__ float sB[D_STATE], sC[D_STATE];
    float Dh = D_skip[h];
    for (int t = 0; t < TE; t++) {
        long rbase = (long)(b*TE + t);
        const float* row = g_xbc + rbase * CONV_CH;
        if (p < D_STATE) sB[p] = row[D_MODEL + p];
        else if (p < 2*D_STATE) sC[p - D_STATE] = row[D_MODEL + p];
        __syncthreads();
        float x   = row[h * HEADDIM + p];
        float dAv = g_dA[rbase * NHEADS + h];
        float coef = g_dt[rbase * NHEADS + h] * x;
        float a0 = 0.f, a1 = 0.f, a2 = 0.f, a3 = 0.f;
#pragma unroll
        for (int n = 0; n < D_STATE; n += 4) {
            hs[n+0] = dAv * hs[n+0] + coef * sB[n+0]; a0 += hs[n+0] * sC[n+0];
            hs[n+1] = dAv * hs[n+1] + coef * sB[n+1]; a1 += hs[n+1] * sC[n+1];
            hs[n+2] = dAv * hs[n+2] + coef * sB[n+2]; a2 += hs[n+2] * sC[n+2];
            hs[n+3] = dAv * hs[n+3] + coef * sB[n+3]; a3 += hs[n+3] * sC[n+3];
        }
        g_y[rbase * D_MODEL + h * HEADDIM + p] = (a0 + a1) + (a2 + a3) + Dh * x;
        __syncthreads();
    }
}

// ---------------- y * silu(z), rmsnorm(ssm_norm_w) ----------------
__global__ void k_gatenorm(const float* __restrict__ w) {
    int row = blockIdx.x;
    const float* yr = g_y + (long)row * D_MODEL;
    const float* zr = g_zx + (long)row * DIN;   // z is first D_MODEL of zxbcdt
    float vals[8];
    float ss = 0.f;
#pragma unroll
    for (int q = 0; q < 8; q++) {
        int j = threadIdx.x + q * 256;
        float z = zr[j];
        float v = yr[j] * siluf(z);
        vals[q] = v; ss += v * v;
    }
    __shared__ float sred[8];
    for (int o = 16; o > 0; o >>= 1) ss += __shfl_down_sync(0xffffffffu, ss, o);
    if ((threadIdx.x & 31) == 0) sred[threadIdx.x >> 5] = ss;
    __syncthreads();
    if (threadIdx.x < 8) {
        float t = sred[threadIdx.x];
        t += __shfl_down_sync(0xffu, t, 4);
        t += __shfl_down_sync(0xffu, t, 2);
        t += __shfl_down_sync(0xffu, t, 1);
        if (threadIdx.x == 0) sred[0] = t;
    }
    __syncthreads();
    float scale = rsqrtf(sred[0] / (float)D_MODEL + 1e-6f);
#pragma unroll
    for (int q = 0; q < 8; q++) {
        int j = threadIdx.x + q * 256;
        g_nrm[(long)row * D_MODEL + j] = vals[q] * scale * w[j];
    }
}

// ---------------- xe = rmsnorm(xe + mamba_out, loop_norm_w) in place ----------------
__global__ void k_addnorm(const float* __restrict__ w) {
    int row = blockIdx.x;
    float vals[8];
    float ss = 0.f;
#pragma unroll
    for (int q = 0; q < 8; q++) {
        int j = threadIdx.x + q * 256;
        float v = g_xe[(long)row * D_MODEL + j] + g_mo[(long)row * D_MODEL + j];
        vals[q] = v; ss += v * v;
    }
    __shared__ float sred[8];
    for (int o = 16; o > 0; o >>= 1) ss += __shfl_down_sync(0xffffffffu, ss, o);
    if ((threadIdx.x & 31) == 0) sred[threadIdx.x >> 5] = ss;
    __syncthreads();
    if (threadIdx.x < 8) {
        float t = sred[threadIdx.x];
        t += __shfl_down_sync(0xffu, t, 4);
        t += __shfl_down_sync(0xffu, t, 2);
        t += __shfl_down_sync(0xffu, t, 1);
        if (threadIdx.x == 0) sred[0] = t;
    }
    __syncthreads();
    float scale = rsqrtf(sred[0] / (float)D_MODEL + 1e-6f);
#pragma unroll
    for (int q = 0; q < 8; q++) {
        int j = threadIdx.x + q * 256;
        g_xe[(long)row * D_MODEL + j] = vals[q] * scale * w[j];
    }
}

// ---------------- bridge down: t1 = xe @ down^T (rank 64) ----------------
__global__ void k_bridge_down(const float* __restrict__ down) {
    int m = blockIdx.x;
    int r = threadIdx.x >> 2;
    int part = threadIdx.x & 3;
    const float* xr = g_xe + (long)m * D_MODEL;
    const float* dr = down + r * D_MODEL;
    float acc = 0.f;
    int k0 = part * 512;
    for (int k = k0; k < k0 + 512; k++) acc += xr[k] * dr[k];
    acc += __shfl_down_sync(0xffffffffu, acc, 1);
    acc += __shfl_down_sync(0xffffffffu, acc, 2);
    if (part == 0) g_t1[m * BRIDGE_RANK + r] = acc;
}

// ---------------- bridge up + residual + extract t>=M rows → g_fin ----------------
__global__ void k_bridge_up(const float* __restrict__ up) {
    int ro = blockIdx.x;               // 0..1023 output row
    int jc = blockIdx.y;               // 0..7
    int b = ro >> 9, t = M_PREFIX + (ro & 511);
    int m = b * TE + t;
    __shared__ float s1[BRIDGE_RANK];
    if (threadIdx.x < BRIDGE_RANK) s1[threadIdx.x] = g_t1[m * BRIDGE_RANK + threadIdx.x];
    __syncthreads();
    int j = jc * 256 + threadIdx.x;
    float acc = g_xe[(long)m * D_MODEL + j];
#pragma unroll
    for (int r = 0; r < BRIDGE_RANK; r++) acc += s1[r] * up[j * BRIDGE_RANK + r];
    g_fin[(long)ro * D_MODEL + j] = acc;
}

// ---------------- launch ----------------
extern "C" void kernel_launch(void* const* d_in, const int* in_sizes, int n_in,
                              void* d_out, int out_size) {
    const int*   ids         = (const int*)  d_in[0];
    const float* emb         = (const float*)d_in[1];
    const float* latent      = (const float*)d_in[2];
    const float* gate        = (const float*)d_in[3];
    const float* loop_norm_w = (const float*)d_in[4];
    const float* in_base     = (const float*)d_in[5];
    const float* in_A        = (const float*)d_in[6];
    const float* in_B        = (const float*)d_in[7];
    const float* conv_w      = (const float*)d_in[8];
    const float* conv_b      = (const float*)d_in[9];
    const float* dt_bias     = (const float*)d_in[10];
    const float* A_log       = (const float*)d_in[11];
    const float* D_skip      = (const float*)d_in[12];
    const float* ssm_norm_w  = (const float*)d_in[13];
    const float* out_base    = (const float*)d_in[14];
    const float* out_A       = (const float*)d_in[15];
    const float* out_B       = (const float*)d_in[16];
    const float* bridge_down = (const float*)d_in[17];
    const float* bridge_up   = (const float*)d_in[18];
    float* out = (float*)d_out;

    float *pWin, *pWout, *pXe, *pNrm, *pZx, *pMo, *pFin;
    cudaGetSymbolAddress((void**)&pWin,  g_Win);
    cudaGetSymbolAddress((void**)&pWout, g_Wout);
    cudaGetSymbolAddress((void**)&pXe,   g_xe);
    cudaGetSymbolAddress((void**)&pNrm,  g_nrm);
    cudaGetSymbolAddress((void**)&pZx,   g_zx);
    cudaGetSymbolAddress((void**)&pMo,   g_mo);
    cudaGetSymbolAddress((void**)&pFin,  g_fin);

    k_lora<<<(DIN * D_MODEL + 255) / 256, 256>>>(in_base, in_A, in_B, pWin, DIN);
    k_lora<<<(D_MODEL * D_MODEL + 255) / 256, 256>>>(out_base, out_A, out_B, pWout, D_MODEL);
    k_embed<<<(ROWS * D_MODEL + 255) / 256, 256>>>(ids, emb, latent);

    for (int li = 0; li < MAX_LOOPS; li++) {
        k_prerope<<<ROWS, 1024>>>(gate, (float)li);
        sgemm_nt<<<dim3((DIN + BN - 1) / BN, (ROWS + BM - 1) / BM), 256>>>(
            pXe, pWin, pZx, ROWS, DIN, D_MODEL);
        k_dt<<<(ROWS * NHEADS + 255) / 256, 256>>>(dt_bias, A_log);
        k_conv<<<(ROWS * CONV_CH + 255) / 256, 256>>>(conv_w, conv_b);
        k_scan<<<BSZ * NHEADS, HEADDIM>>>(D_skip);
        k_gatenorm<<<ROWS, 256>>>(ssm_norm_w);
        sgemm_nt<<<dim3(D_MODEL / BN, (ROWS + BM - 1) / BM), 256>>>(
            pNrm, pWout, pMo, ROWS, D_MODEL, D_MODEL);
        k_addnorm<<<ROWS, 256>>>(loop_norm_w);
    }

    k_bridge_down<<<ROWS, 256>>>(bridge_down);
    k_bridge_up<<<dim3(OUTROWS, D_MODEL / 256), 256>>>(bridge_up);
    sgemm_nt<<<dim3(VOCAB / BN, OUTROWS / BM), 256>>>(pFin, emb, out, OUTROWS, VOCAB, D_MODEL);
}

// round 3
// speedup vs baseline: 2.1578x; 2.1578x over previous
#include <cuda_runtime.h>
#include <cuda_bf16.h>
#include <math.h>
#include <stdint.h>

#define D_MODEL 2048
#define D_STATE 32
#define HEADDIM 128
#define NHEADS 16
#define D_CONVK 4
#define M_PREFIX 8
#define MAX_LOOPS 6
#define BRIDGE_RANK 64
#define VOCAB 50432
#define LORA_RANK 4
#define BSZ 2
#define TLEN 512
#define TE (M_PREFIX + TLEN)     /* 520 */
#define ROWS (BSZ * TE)          /* 1040 */
#define DIN (2*D_MODEL + 2*D_STATE + NHEADS)  /* 4176 */
#define CONV_CH (D_MODEL + 2*D_STATE)         /* 2112 */
#define OUTROWS (BSZ * TLEN)     /* 1024 */

// ---------------- scratch (static device globals; no allocs) ----------------
__device__ float g_Win[DIN * D_MODEL];
__device__ float g_Wout[D_MODEL * D_MODEL];
__device__ float g_xe[ROWS * D_MODEL];
__device__ float g_xp[OUTROWS * D_MODEL];
__device__ float g_zx[ROWS * DIN];
__device__ float g_xbc[ROWS * CONV_CH];
__device__ float g_dt[ROWS * NHEADS];
__device__ float g_dA[ROWS * NHEADS];
__device__ float g_y[ROWS * D_MODEL];
__device__ float g_nrm[ROWS * D_MODEL];
__device__ float g_mo[ROWS * D_MODEL];
__device__ float g_t1[ROWS * BRIDGE_RANK];
__device__ float g_fin[OUTROWS * D_MODEL];

__device__ __forceinline__ float siluf(float x) { return x / (1.0f + expf(-x)); }

__device__ __forceinline__ uint32_t smem_u32(const void* p) {
    uint32_t a;
    asm("{ .reg .u64 t; cvta.to.shared.u64 t, %1; cvt.u32.u64 %0, t; }" : "=r"(a) : "l"(p));
    return a;
}

// pack two f32 -> bf16x2 (lo in low 16 bits, hi in high 16 bits)
__device__ __forceinline__ uint32_t cvt2bf(float lo, float hi) {
    uint32_t r;
    asm("cvt.rn.bf16x2.f32 %0, %1, %2;" : "=r"(r) : "f"(hi), "f"(lo));
    return r;
}

// ================= bf16x3 mma.sync GEMM: C = A @ B^T =================
// A: MxK f32 row-major, B: NxK f32 row-major, C: MxN f32 row-major. K % 32 == 0.
// CTA tile 128x128, warp tile 64x32, K-chunk 32. smem row stride 40 bf16 (80B).
#define KC 32
#define SROW 40

__device__ __forceinline__ void split_store(__nv_bfloat16* hi, __nv_bfloat16* lo,
                                            int row, int c4, float4 v) {
    uint2 ph, pl;
    ph.x = cvt2bf(v.x, v.y);
    ph.y = cvt2bf(v.z, v.w);
    float h0 = __uint_as_float(ph.x << 16);
    float h1 = __uint_as_float(ph.x & 0xFFFF0000u);
    float h2 = __uint_as_float(ph.y << 16);
    float h3 = __uint_as_float(ph.y & 0xFFFF0000u);
    pl.x = cvt2bf(v.x - h0, v.y - h1);
    pl.y = cvt2bf(v.z - h2, v.w - h3);
    *(uint2*)(hi + row * SROW + c4 * 4) = ph;
    *(uint2*)(lo + row * SROW + c4 * 4) = pl;
}

#define LDSM4(r, addr) \
    asm volatile("ldmatrix.sync.aligned.m8n8.x4.shared.b16 {%0,%1,%2,%3}, [%4];" \
        : "=r"((r)[0]), "=r"((r)[1]), "=r"((r)[2]), "=r"((r)[3]) : "r"(addr))

#define MMA16816(d, a, b0, b1) \
    asm volatile("mma.sync.aligned.m16n8k16.row.col.f32.bf16.bf16.f32 " \
        "{%0,%1,%2,%3},{%4,%5,%6,%7},{%8,%9},{%0,%1,%2,%3};" \
        : "+f"((d)[0]), "+f"((d)[1]), "+f"((d)[2]), "+f"((d)[3]) \
        : "r"((a)[0]), "r"((a)[1]), "r"((a)[2]), "r"((a)[3]), "r"(b0), "r"(b1))

__global__ void __launch_bounds__(256, 2) gemm_bf3(const float* __restrict__ A,
                                                   const float* __restrict__ B,
                                                   float* __restrict__ C,
                                                   int M, int N, int K) {
    __shared__ __align__(16) __nv_bfloat16 sAH[128 * SROW];
    __shared__ __align__(16) __nv_bfloat16 sAL[128 * SROW];
    __shared__ __align__(16) __nv_bfloat16 sBH[128 * SROW];
    __shared__ __align__(16) __nv_bfloat16 sBL[128 * SROW];

    int tid = threadIdx.x, lane = tid & 31, wid = tid >> 5;
    int wm = wid >> 2, wn = wid & 3;     // 2 x 4 warp grid
    int m0 = blockIdx.y * 128, n0 = blockIdx.x * 128;

    float acc[4][4][4] = {};

    uint32_t uAH = smem_u32(sAH), uAL = smem_u32(sAL);
    uint32_t uBH = smem_u32(sBH), uBL = smem_u32(sBL);

    // ldmatrix base offsets (bytes), per-lane
    // A: row = wm*64 + mt*16 + (lane&15); col = ks*16 + (lane>>4)*8
    uint32_t aRow = (uint32_t)(wm * 64 + (lane & 15));
    uint32_t aColB = (uint32_t)((lane >> 4) * 8) * 2;
    // B: row = wn*32 + bt*16 + ((lane>>4)&1)*8 + (lane&7); col = ks*16 + ((lane>>3)&1)*8
    uint32_t bRow = (uint32_t)(wn * 32 + ((lane >> 4) & 1) * 8 + (lane & 7));
    uint32_t bColB = (uint32_t)(((lane >> 3) & 1) * 8) * 2;

    for (int k0 = 0; k0 < K; k0 += KC) {
        __syncthreads();
#pragma unroll
        for (int it = 0; it < 4; it++) {
            int idx = tid + it * 256;
            int row = idx >> 3, c4 = idx & 7;
            int gm = m0 + row;
            float4 v = make_float4(0.f, 0.f, 0.f, 0.f);
            if (gm < M) v = *(const float4*)(A + (size_t)gm * K + k0 + c4 * 4);
            split_store(sAH, sAL, row, c4, v);
            int gn = n0 + row;
            float4 w = make_float4(0.f, 0.f, 0.f, 0.f);
            if (gn < N) w = *(const float4*)(B + (size_t)gn * K + k0 + c4 * 4);
            split_store(sBH, sBL, row, c4, w);
        }
        __syncthreads();

#pragma unroll
        for (int ks = 0; ks < 2; ks++) {
            uint32_t kcb = (uint32_t)(ks * 16) * 2;
            uint32_t a[4][4], a2[4][4], b[2][4];
            // --- load Ah frags ---
#pragma unroll
            for (int mt = 0; mt < 4; mt++) {
                uint32_t addr = uAH + ((aRow + mt * 16) * SROW) * 2 + kcb + aColB;
                LDSM4(a[mt], addr);
            }
            // --- load Bh frags ---
#pragma unroll
            for (int bt = 0; bt < 2; bt++) {
                uint32_t addr = uBH + ((bRow + bt * 16) * SROW) * 2 + kcb + bColB;
                LDSM4(b[bt], addr);
            }
            // pass 1: Ah * Bh
#pragma unroll
            for (int mt = 0; mt < 4; mt++)
#pragma unroll
                for (int nt = 0; nt < 4; nt++)
                    MMA16816(acc[mt][nt], a[mt], b[nt >> 1][(nt & 1) * 2], b[nt >> 1][(nt & 1) * 2 + 1]);
            // --- load Al frags ---
#pragma unroll
            for (int mt = 0; mt < 4; mt++) {
                uint32_t addr = uAL + ((aRow + mt * 16) * SROW) * 2 + kcb + aColB;
                LDSM4(a2[mt], addr);
            }
            // pass 2: Al * Bh
#pragma unroll
            for (int mt = 0; mt < 4; mt++)
#pragma unroll
                for (int nt = 0; nt < 4; nt++)
                    MMA16816(acc[mt][nt], a2[mt], b[nt >> 1][(nt & 1) * 2], b[nt >> 1][(nt & 1) * 2 + 1]);
            // --- load Bl frags (reuse b) ---
#pragma unroll
            for (int bt = 0; bt < 2; bt++) {
                uint32_t addr = uBL + ((bRow + bt * 16) * SROW) * 2 + kcb + bColB;
                LDSM4(b[bt], addr);
            }
            // pass 3: Ah * Bl
#pragma unroll
            for (int mt = 0; mt < 4; mt++)
#pragma unroll
                for (int nt = 0; nt < 4; nt++)
                    MMA16816(acc[mt][nt], a[mt], b[nt >> 1][(nt & 1) * 2], b[nt >> 1][(nt & 1) * 2 + 1]);
        }
    }

    // ---- epilogue: direct f32 stores ----
#pragma unroll
    for (int mt = 0; mt < 4; mt++) {
#pragma unroll
        for (int nt = 0; nt < 4; nt++) {
            int m = m0 + wm * 64 + mt * 16 + (lane >> 2);
            int n = n0 + wn * 32 + nt * 8 + (lane & 3) * 2;
            if (n < N) {
                if (m < M) {
                    float2 v = make_float2(acc[mt][nt][0], acc[mt][nt][1]);
                    *(float2*)(C + (size_t)m * N + n) = v;
                }
                if (m + 8 < M) {
                    float2 v = make_float2(acc[mt][nt][2], acc[mt][nt][3]);
                    *(float2*)(C + (size_t)(m + 8) * N + n) = v;
                }
            }
        }
    }
}

// ---------------- LoRA weight fold: W = base + 2 * (B @ A) ----------------
__global__ void k_lora(const float* __restrict__ base, const float* __restrict__ Amat,
                       const float* __restrict__ Bmat, float* __restrict__ W, int rows) {
    int i = blockIdx.x * 256 + threadIdx.x;
    if (i >= rows * D_MODEL) return;
    int r = i / D_MODEL, c = i % D_MODEL;
    float s = 0.f;
#pragma unroll
    for (int q = 0; q < LORA_RANK; q++) s += Bmat[r*LORA_RANK + q] * Amat[q*D_MODEL + c];
    W[i] = base[i] + 2.0f * s;
}

// ---------------- embedding gather + latent prefix ----------------
__global__ void k_embed(const int* __restrict__ ids, const float* __restrict__ emb,
                        const float* __restrict__ latent) {
    int i = blockIdx.x * 256 + threadIdx.x;
    if (i >= ROWS * D_MODEL) return;
    int row = i / D_MODEL, c = i % D_MODEL;
    int b = row / TE, t = row % TE;
    float v;
    if (t < M_PREFIX) {
        v = latent[t * D_MODEL + c];
    } else {
        int tok = ids[b * TLEN + (t - M_PREFIX)];
        v = emb[(long)tok * D_MODEL + c];
        g_xp[(b * TLEN + (t - M_PREFIX)) * D_MODEL + c] = v;
    }
    g_xe[i] = v;
}

// ---------------- lifeline add (t>=M) + interleaved RoPE, in place ----------------
__global__ void k_prerope(const float* __restrict__ gate, float loop_i) {
    int row = blockIdx.x;
    int j = threadIdx.x;              // pair index 0..1023
    int b = row / TE, t = row % TE;
    float v0 = g_xe[row * D_MODEL + 2*j];
    float v1 = g_xe[row * D_MODEL + 2*j + 1];
    if (t >= M_PREFIX) {
        int pr = (b * TLEN + t - M_PREFIX) * D_MODEL;
        v0 += gate[2*j]     * g_xp[pr + 2*j];
        v1 += gate[2*j + 1] * g_xp[pr + 2*j + 1];
    }
    float freq = loop_i * powf(10000.0f, -(float)(2*j) / (float)D_MODEL);
    float s, c;
    sincosf(freq, &s, &c);
    g_xe[row * D_MODEL + 2*j]     = v0 * c - v1 * s;
    g_xe[row * D_MODEL + 2*j + 1] = v1 * c + v0 * s;
}

// ---------------- dt = softplus(raw + bias), dA = exp(-exp(A_log)*dt) ----------------
__global__ void k_dt(const float* __restrict__ dt_bias, const float* __restrict__ A_log) {
    int i = blockIdx.x * 256 + threadIdx.x;
    if (i >= ROWS * NHEADS) return;
    int row = i / NHEADS, h = i % NHEADS;
    float x = g_zx[(long)row * DIN + (2*D_MODEL + 2*D_STATE) + h] + dt_bias[h];
    float sp = (x > 20.f) ? x : log1pf(expf(x));
    g_dt[i] = sp;
    g_dA[i] = expf(-expf(A_log[h]) * sp);
}

// ---------------- depthwise causal conv (K=4) + bias + silu ----------------
__global__ void k_conv(const float* __restrict__ cw, const float* __restrict__ cb) {
    int i = blockIdx.x * 256 + threadIdx.x;
    if (i >= ROWS * CONV_CH) return;
    int row = i / CONV_CH, c = i % CONV_CH;
    int b = row / TE, t = row % TE;
    float acc = cb[c];
#pragma unroll
    for (int k = 0; k < D_CONVK; k++) {
        int tt = t - (D_CONVK - 1) + k;
        if (tt >= 0) acc += g_zx[((long)(b*TE + tt)) * DIN + D_MODEL + c] * cw[c*D_CONVK + k];
    }
    g_xbc[i] = siluf(acc);
}

// ---------------- sequential SSM scan with register/smem prefetch ----------------
__global__ void k_scan(const float* __restrict__ D_skip) {
    int b = blockIdx.x >> 4;
    int h = blockIdx.x & 15;
    int p = threadIdx.x;
    float hs[D_STATE];
#pragma unroll
    for (int n = 0; n < D_STATE; n++) hs[n] = 0.f;
    __shared__ float sB[2][D_STATE], sC[2][D_STATE];
    float Dh = D_skip[h];

    const float* row0 = g_xbc + (long)(b*TE) * CONV_CH;
    if (p < 2*D_STATE) {
        float v = row0[D_MODEL + p];
        if (p < D_STATE) sB[0][p] = v; else sC[0][p - D_STATE] = v;
    }
    float x   = row0[h * HEADDIM + p];
    float dAv = g_dA[(long)(b*TE) * NHEADS + h];
    float dtv = g_dt[(long)(b*TE) * NHEADS + h];
    __syncthreads();

    for (int t = 0; t < TE; t++) {
        int tn = (t + 1 < TE) ? t + 1 : t;
        long rn = (long)(b*TE + tn);
        const float* rown = g_xbc + rn * CONV_CH;
        float xn   = rown[h * HEADDIM + p];
        float dAn  = g_dA[rn * NHEADS + h];
        float dtn  = g_dt[rn * NHEADS + h];
        int nxt = (t + 1) & 1, cur = t & 1;
        if (p < 2*D_STATE) {
            float v = rown[D_MODEL + p];
            if (p < D_STATE) sB[nxt][p] = v; else sC[nxt][p - D_STATE] = v;
        }
        float coef = dtv * x;
        float a0 = 0.f, a1 = 0.f, a2 = 0.f, a3 = 0.f;
#pragma unroll
        for (int n = 0; n < D_STATE; n += 4) {
            hs[n+0] = dAv * hs[n+0] + coef * sB[cur][n+0]; a0 += hs[n+0] * sC[cur][n+0];
            hs[n+1] = dAv * hs[n+1] + coef * sB[cur][n+1]; a1 += hs[n+1] * sC[cur][n+1];
            hs[n+2] = dAv * hs[n+2] + coef * sB[cur][n+2]; a2 += hs[n+2] * sC[cur][n+2];
            hs[n+3] = dAv * hs[n+3] + coef * sB[cur][n+3]; a3 += hs[n+3] * sC[cur][n+3];
        }
        g_y[(long)(b*TE + t) * D_MODEL + h * HEADDIM + p] = (a0 + a1) + (a2 + a3) + Dh * x;
        __syncthreads();
        x = xn; dAv = dAn; dtv = dtn;
    }
}

// ---------------- y * silu(z), rmsnorm(ssm_norm_w) ----------------
__global__ void k_gatenorm(const float* __restrict__ w) {
    int row = blockIdx.x;
    const float* yr = g_y + (long)row * D_MODEL;
    const float* zr = g_zx + (long)row * DIN;
    float vals[8];
    float ss = 0.f;
#pragma unroll
    for (int q = 0; q < 8; q++) {
        int j = threadIdx.x + q * 256;
        float z = zr[j];
        float v = yr[j] * siluf(z);
        vals[q] = v; ss += v * v;
    }
    __shared__ float sred[8];
    for (int o = 16; o > 0; o >>= 1) ss += __shfl_down_sync(0xffffffffu, ss, o);
    if ((threadIdx.x & 31) == 0) sred[threadIdx.x >> 5] = ss;
    __syncthreads();
    if (threadIdx.x < 8) {
        float t = sred[threadIdx.x];
        t += __shfl_down_sync(0xffu, t, 4);
        t += __shfl_down_sync(0xffu, t, 2);
        t += __shfl_down_sync(0xffu, t, 1);
        if (threadIdx.x == 0) sred[0] = t;
    }
    __syncthreads();
    float scale = rsqrtf(sred[0] / (float)D_MODEL + 1e-6f);
#pragma unroll
    for (int q = 0; q < 8; q++) {
        int j = threadIdx.x + q * 256;
        g_nrm[(long)row * D_MODEL + j] = vals[q] * scale * w[j];
    }
}

// ---------------- xe = rmsnorm(xe + mamba_out, loop_norm_w) in place ----------------
__global__ void k_addnorm(const float* __restrict__ w) {
    int row = blockIdx.x;
    float vals[8];
    float ss = 0.f;
#pragma unroll
    for (int q = 0; q < 8; q++) {
        int j = threadIdx.x + q * 256;
        float v = g_xe[(long)row * D_MODEL + j] + g_mo[(long)row * D_MODEL + j];
        vals[q] = v; ss += v * v;
    }
    __shared__ float sred[8];
    for (int o = 16; o > 0; o >>= 1) ss += __shfl_down_sync(0xffffffffu, ss, o);
    if ((threadIdx.x & 31) == 0) sred[threadIdx.x >> 5] = ss;
    __syncthreads();
    if (threadIdx.x < 8) {
        float t = sred[threadIdx.x];
        t += __shfl_down_sync(0xffu, t, 4);
        t += __shfl_down_sync(0xffu, t, 2);
        t += __shfl_down_sync(0xffu, t, 1);
        if (threadIdx.x == 0) sred[0] = t;
    }
    __syncthreads();
    float scale = rsqrtf(sred[0] / (float)D_MODEL + 1e-6f);
#pragma unroll
    for (int q = 0; q < 8; q++) {
        int j = threadIdx.x + q * 256;
        g_xe[(long)row * D_MODEL + j] = vals[q] * scale * w[j];
    }
}

// ---------------- bridge down: t1 = xe @ down^T (rank 64) ----------------
__global__ void k_bridge_down(const float* __restrict__ down) {
    int m = blockIdx.x;
    int r = threadIdx.x >> 2;
    int part = threadIdx.x & 3;
    const float* xr = g_xe + (long)m * D_MODEL;
    const float* dr = down + r * D_MODEL;
    float acc = 0.f;
    int k0 = part * 512;
    for (int k = k0; k < k0 + 512; k++) acc += xr[k] * dr[k];
    acc += __shfl_down_sync(0xffffffffu, acc, 1);
    acc += __shfl_down_sync(0xffffffffu, acc, 2);
    if (part == 0) g_t1[m * BRIDGE_RANK + r] = acc;
}

// ---------------- bridge up + residual + extract t>=M rows → g_fin ----------------
__global__ void k_bridge_up(const float* __restrict__ up) {
    int ro = blockIdx.x;
    int jc = blockIdx.y;
    int b = ro >> 9, t = M_PREFIX + (ro & 511);
    int m = b * TE + t;
    __shared__ float s1[BRIDGE_RANK];
    if (threadIdx.x < BRIDGE_RANK) s1[threadIdx.x] = g_t1[m * BRIDGE_RANK + threadIdx.x];
    __syncthreads();
    int j = jc * 256 + threadIdx.x;
    float acc = g_xe[(long)m * D_MODEL + j];
#pragma unroll
    for (int r = 0; r < BRIDGE_RANK; r++) acc += s1[r] * up[j * BRIDGE_RANK + r];
    g_fin[(long)ro * D_MODEL + j] = acc;
}

// ---------------- launch ----------------
extern "C" void kernel_launch(void* const* d_in, const int* in_sizes, int n_in,
                              void* d_out, int out_size) {
    const int*   ids         = (const int*)  d_in[0];
    const float* emb         = (const float*)d_in[1];
    const float* latent      = (const float*)d_in[2];
    const float* gate        = (const float*)d_in[3];
    const float* loop_norm_w = (const float*)d_in[4];
    const float* in_base     = (const float*)d_in[5];
    const float* in_A        = (const float*)d_in[6];
    const float* in_B        = (const float*)d_in[7];
    const float* conv_w      = (const float*)d_in[8];
    const float* conv_b      = (const float*)d_in[9];
    const float* dt_bias     = (const float*)d_in[10];
    const float* A_log       = (const float*)d_in[11];
    const float* D_skip      = (const float*)d_in[12];
    const float* ssm_norm_w  = (const float*)d_in[13];
    const float* out_base    = (const float*)d_in[14];
    const float* out_A       = (const float*)d_in[15];
    const float* out_B       = (const float*)d_in[16];
    const float* bridge_down = (const float*)d_in[17];
    const float* bridge_up   = (const float*)d_in[18];
    float* out = (float*)d_out;

    float *pWin, *pWout, *pXe, *pNrm, *pZx, *pMo, *pFin;
    cudaGetSymbolAddress((void**)&pWin,  g_Win);
    cudaGetSymbolAddress((void**)&pWout, g_Wout);
    cudaGetSymbolAddress((void**)&pXe,   g_xe);
    cudaGetSymbolAddress((void**)&pNrm,  g_nrm);
    cudaGetSymbolAddress((void**)&pZx,   g_zx);
    cudaGetSymbolAddress((void**)&pMo,   g_mo);
    cudaGetSymbolAddress((void**)&pFin,  g_fin);

    k_lora<<<(DIN * D_MODEL + 255) / 256, 256>>>(in_base, in_A, in_B, pWin, DIN);
    k_lora<<<(D_MODEL * D_MODEL + 255) / 256, 256>>>(out_base, out_A, out_B, pWout, D_MODEL);
    k_embed<<<(ROWS * D_MODEL + 255) / 256, 256>>>(ids, emb, latent);

    for (int li = 0; li < MAX_LOOPS; li++) {
        k_prerope<<<ROWS, 1024>>>(gate, (float)li);
        gemm_bf3<<<dim3((DIN + 127) / 128, (ROWS + 127) / 128), 256>>>(
            pXe, pWin, pZx, ROWS, DIN, D_MODEL);
        k_dt<<<(ROWS * NHEADS + 255) / 256, 256>>>(dt_bias, A_log);
        k_conv<<<(ROWS * CONV_CH + 255) / 256, 256>>>(conv_w, conv_b);
        k_scan<<<BSZ * NHEADS, HEADDIM>>>(D_skip);
        k_gatenorm<<<ROWS, 256>>>(ssm_norm_w);
        gemm_bf3<<<dim3(D_MODEL / 128, (ROWS + 127) / 128), 256>>>(
            pNrm, pWout, pMo, ROWS, D_MODEL, D_MODEL);
        k_addnorm<<<ROWS, 256>>>(loop_norm_w);
    }

    k_bridge_down<<<ROWS, 256>>>(bridge_down);
    k_bridge_up<<<dim3(OUTROWS, D_MODEL / 256), 256>>>(bridge_up);
    gemm_bf3<<<dim3(VOCAB / 128, OUTROWS / 128), 256>>>(
        pFin, emb, out, OUTROWS, VOCAB, D_MODEL);
}